// round 9
// baseline (speedup 1.0000x reference)
#include <cuda_runtime.h>

// out[b,f] = x[b,f] * (log_sigma[f] < 1.0f ? e : 1.0f)
// BATCH=65536, N_FEATURES=4096 -> 2^26 float4. Pure HBM stream (2.15 GB).
//
// R9: extend R8's winning mechanism (fine-grained launch + front-batched
// independent loads) to 4 float4/thread, straight-line: 65536 blocks x 256,
// 4 back-to-back LDG.128 (MLP_p1=4), then 4 STG.128. Low regs, no loop.
//
// All four elements share one column index (stride 2^24 % 1024 == 0),
// so one log_sigma load per thread.

#define N_FEATURES   4096
#define VEC4_PER_ROW (N_FEATURES / 4)            // 1024, power of two
#define TOTAL_VEC4   (65536LL * VEC4_PER_ROW)    // 2^26

#define THREADS  256
#define BLOCKS   65536                            // 2^24 threads
#define NSTRIDE  ((long long)THREADS * BLOCKS)    // 2^24, multiple of 1024

__global__ void __launch_bounds__(THREADS)
svdropout2d_kernel(const float4* __restrict__ x,
                   const float4* __restrict__ log_sigma,
                   float4* __restrict__ out)
{
    const float E = 2.71828182845904523536f;

    const long long i = (long long)blockIdx.x * THREADS + threadIdx.x;

    // Same column for all 4 elements (stride % 1024 == 0): one scale load.
    const int c = (int)(i & (VEC4_PER_ROW - 1));
    const float4 ls = __ldg(&log_sigma[c]);

    float4 s;
    s.x = (ls.x < 1.0f) ? E : 1.0f;
    s.y = (ls.y < 1.0f) ? E : 1.0f;
    s.z = (ls.z < 1.0f) ? E : 1.0f;
    s.w = (ls.w < 1.0f) ? E : 1.0f;

    // Front-batched independent loads (MLP_p1 = 4)
    float4 v0 = x[i + 0 * NSTRIDE];
    float4 v1 = x[i + 1 * NSTRIDE];
    float4 v2 = x[i + 2 * NSTRIDE];
    float4 v3 = x[i + 3 * NSTRIDE];

    v0.x *= s.x; v0.y *= s.y; v0.z *= s.z; v0.w *= s.w;
    v1.x *= s.x; v1.y *= s.y; v1.z *= s.z; v1.w *= s.w;
    v2.x *= s.x; v2.y *= s.y; v2.z *= s.z; v2.w *= s.w;
    v3.x *= s.x; v3.y *= s.y; v3.z *= s.z; v3.w *= s.w;

    out[i + 0 * NSTRIDE] = v0;
    out[i + 1 * NSTRIDE] = v1;
    out[i + 2 * NSTRIDE] = v2;
    out[i + 3 * NSTRIDE] = v3;
}

extern "C" void kernel_launch(void* const* d_in, const int* in_sizes, int n_in,
                              void* d_out, int out_size)
{
    const float4* x  = (const float4*)d_in[0];
    const float4* ls = (const float4*)d_in[1];
    float4* out      = (float4*)d_out;

    svdropout2d_kernel<<<BLOCKS, THREADS>>>(x, ls, out);
}

// round 10
// speedup vs baseline: 1.0148x; 1.0148x over previous
#include <cuda_runtime.h>

// out[b,f] = x[b,f] * (log_sigma[f] < 1.0f ? e : 1.0f)
// BATCH=65536, N_FEATURES=4096 -> 2^26 float4. Pure HBM stream (2.15 GB).
//
// R10: R8's winning mechanism (fine-grained launch, 2 front-batched
// independent float4 loads per thread = MLP_p1=2, the measured DRAM-
// efficiency sweet spot: 88.2% vs 83% @MLP1 / 87.1% @MLP4) with 512-thread
// blocks: same 2^25 threads in half the CTAs -> less scheduler churn,
// better warp-slot packing, identical addressing.

#define N_FEATURES   4096
#define VEC4_PER_ROW (N_FEATURES / 4)            // 1024, power of two
#define TOTAL_VEC4   (65536LL * VEC4_PER_ROW)    // 2^26

#define THREADS  512
#define BLOCKS   65536                            // 2^25 threads total
#define NSTRIDE  ((long long)THREADS * BLOCKS)    // 2^25, multiple of 1024

__global__ void __launch_bounds__(THREADS)
svdropout2d_kernel(const float4* __restrict__ x,
                   const float4* __restrict__ log_sigma,
                   float4* __restrict__ out)
{
    const float E = 2.71828182845904523536f;

    const long long i = (long long)blockIdx.x * THREADS + threadIdx.x;

    // Same column for both elements (stride % 1024 == 0): one scale load.
    const int c = (int)(i & (VEC4_PER_ROW - 1));
    const float4 ls = __ldg(&log_sigma[c]);

    float4 s;
    s.x = (ls.x < 1.0f) ? E : 1.0f;
    s.y = (ls.y < 1.0f) ? E : 1.0f;
    s.z = (ls.z < 1.0f) ? E : 1.0f;
    s.w = (ls.w < 1.0f) ? E : 1.0f;

    // Front-batched independent loads (MLP_p1 = 2)
    float4 v0 = x[i];
    float4 v1 = x[i + NSTRIDE];

    v0.x *= s.x; v0.y *= s.y; v0.z *= s.z; v0.w *= s.w;
    v1.x *= s.x; v1.y *= s.y; v1.z *= s.z; v1.w *= s.w;

    out[i]           = v0;
    out[i + NSTRIDE] = v1;
}

extern "C" void kernel_launch(void* const* d_in, const int* in_sizes, int n_in,
                              void* d_out, int out_size)
{
    const float4* x  = (const float4*)d_in[0];
    const float4* ls = (const float4*)d_in[1];
    float4* out      = (float4*)d_out;

    svdropout2d_kernel<<<BLOCKS, THREADS>>>(x, ls, out);
}

// round 11
// speedup vs baseline: 1.0215x; 1.0066x over previous
#include <cuda_runtime.h>

// out[b,f] = x[b,f] * (log_sigma[f] < 1.0f ? e : 1.0f)
// BATCH=65536, N_FEATURES=4096 -> 2^26 float4. Pure HBM stream (2.15 GB).
//
// R11: same winning mechanism (fine-grained, MLP_p1=2 front-batched
// float4 loads — measured DRAM optimum at 88.3% / 7.0 TB/s) with
// 1024-thread blocks: 32768 CTAs (~220/SM leveling granularity),
// per-CTA scheduling overhead halved again vs R10.

#define N_FEATURES   4096
#define VEC4_PER_ROW (N_FEATURES / 4)            // 1024, power of two
#define TOTAL_VEC4   (65536LL * VEC4_PER_ROW)    // 2^26

#define THREADS  1024
#define BLOCKS   32768                            // 2^25 threads total
#define NSTRIDE  ((long long)THREADS * BLOCKS)    // 2^25, multiple of 1024

__global__ void __launch_bounds__(THREADS)
svdropout2d_kernel(const float4* __restrict__ x,
                   const float4* __restrict__ log_sigma,
                   float4* __restrict__ out)
{
    const float E = 2.71828182845904523536f;

    const long long i = (long long)blockIdx.x * THREADS + threadIdx.x;

    // Same column for both elements (stride % 1024 == 0): one scale load.
    const int c = (int)(i & (VEC4_PER_ROW - 1));
    const float4 ls = __ldg(&log_sigma[c]);

    float4 s;
    s.x = (ls.x < 1.0f) ? E : 1.0f;
    s.y = (ls.y < 1.0f) ? E : 1.0f;
    s.z = (ls.z < 1.0f) ? E : 1.0f;
    s.w = (ls.w < 1.0f) ? E : 1.0f;

    // Front-batched independent loads (MLP_p1 = 2)
    float4 v0 = x[i];
    float4 v1 = x[i + NSTRIDE];

    v0.x *= s.x; v0.y *= s.y; v0.z *= s.z; v0.w *= s.w;
    v1.x *= s.x; v1.y *= s.y; v1.z *= s.z; v1.w *= s.w;

    out[i]           = v0;
    out[i + NSTRIDE] = v1;
}

extern "C" void kernel_launch(void* const* d_in, const int* in_sizes, int n_in,
                              void* d_out, int out_size)
{
    const float4* x  = (const float4*)d_in[0];
    const float4* ls = (const float4*)d_in[1];
    float4* out      = (float4*)d_out;

    svdropout2d_kernel<<<BLOCKS, THREADS>>>(x, ls, out);
}